// round 7
// baseline (speedup 1.0000x reference)
#include <cuda_runtime.h>
#include <cstdint>

#define BS 128
#define NR 3
#define CD 64
#define CG 3
#define CH 256
#define KIN 67
#define KTOT 72
#define HW 1024
#define PXT 128
#define THREADS 256
#define NBLK (BS * HW / PXT)   // 1024

// smem layout (floats)
#define SB_OFF   0          // permuted W1^T tf32: 18 k-halves * 8 g * 32 chunks * 4 = 18432
#define XS_OFF   18432      // X tf32 [3 refs][128 px][76 stride] = 29184
#define W3_OFF   47616      // 256
#define SRED_OFF 47872      // [3][2][128] = 768
#define WNM_OFF  48640      // [3][128] = 384
#define SMEM_FLOATS 49024
#define SMEM_BYTES (SMEM_FLOATS * 4)   // 196096

#define XSTRIDE 76
#define XREF (PXT * XSTRIDE)   // 9728

__device__ __forceinline__ float tf32f(float f) {
    uint32_t r; asm("cvt.rna.tf32.f32 %0, %1;" : "=r"(r) : "f"(f));
    return __uint_as_float(r);
}

__device__ __forceinline__ void mma8(float* d, const uint32_t* a, uint32_t b0, uint32_t b1) {
    asm volatile(
        "mma.sync.aligned.m16n8k8.row.col.f32.tf32.tf32.f32 "
        "{%0,%1,%2,%3}, {%4,%5,%6,%7}, {%8,%9}, {%0,%1,%2,%3};"
        : "+f"(d[0]), "+f"(d[1]), "+f"(d[2]), "+f"(d[3])
        : "r"(a[0]), "r"(a[1]), "r"(a[2]), "r"(a[3]), "r"(b0), "r"(b1));
}

extern __shared__ float sm[];

__global__ __launch_bounds__(THREADS, 1)
void qnn_kernel(const float* __restrict__ data, const float* __restrict__ gt,
                const float* __restrict__ W1, const float* __restrict__ b1,
                const float* __restrict__ W3, const float* __restrict__ b3,
                float* __restrict__ out)
{
    float* sB   = sm + SB_OFF;
    float* xs   = sm + XS_OFF;
    float* w3s  = sm + W3_OFF;
    float* sred = sm + SRED_OFF;
    float* wnm  = sm + WNM_OFF;

    const int tid  = threadIdx.x;
    const int lane = tid & 31;
    const int warp = tid >> 5;
    const int mw = warp & 3;          // px block of 32
    const int nh = warp >> 2;         // output half of 128
    const int px0 = mw * 32;
    const int r = lane >> 2;          // 0..7
    const int q = lane & 3;           // 0..3
    const int b  = blockIdx.x >> 3;
    const int p0 = (blockIdx.x & 7) * PXT;

    // ---- stage W1^T (permuted reader-blocks), bias k=67, zero k=68..71 ----
    #pragma unroll 1
    for (int it = 0; it < 72; it++) {
        int i = it * THREADS + tid;           // < 18432
        int n = i / KTOT, kk = i - n * KTOT;
        float v = (kk < KIN) ? W1[n * KIN + kk] : ((kk == KIN) ? b1[n] : 0.f);
        int k8 = kk >> 3, koff = (kk >> 2) & 1, k2 = kk & 3;
        int g = n >> 5, j = (n >> 3) & 3, c = n & 7;
        int blk = (k8 * 2 + koff) * 8 + g;
        sB[(blk * 32 + k2 * 8 + c) * 4 + j] = tf32f(v);
    }
    w3s[tid] = W3[tid];

    // ---- stage X for all 3 refs (tf32), bias col 67, zero 68..71 ----
    #pragma unroll 1
    for (int it = 0; it < 108; it++) {
        int i = it * THREADS + tid;           // < 27648
        int n = i / (PXT * KTOT);
        int rem = i - n * (PXT * KTOT);
        int px = rem & 127, k = rem >> 7;
        float v;
        if (k < CD)       v = data[((size_t)(b * NR + n) * CD + k) * HW + p0 + px];
        else if (k < KIN) v = gt[((size_t)b * CG + (k - CD)) * HW + p0 + px];
        else              v = (k == KIN) ? 1.f : 0.f;
        xs[n * XREF + px * XSTRIDE + k] = tf32f(v);
    }
    const float bias3 = b3[0];
    __syncthreads();

    // ---- 3 refs: MMA + per-ref epilogue (no inter-ref syncs) ----
    #pragma unroll 1
    for (int n = 0; n < NR; n++) {
        float acc[2][16][4];
        #pragma unroll
        for (int mt = 0; mt < 2; mt++)
            #pragma unroll
            for (int nt = 0; nt < 16; nt++)
                #pragma unroll
                for (int e = 0; e < 4; e++) acc[mt][nt][e] = 0.f;

        const float* xr = xs + n * XREF;

        #pragma unroll
        for (int k8 = 0; k8 < 9; k8++) {
            uint32_t a[2][4];
            #pragma unroll
            for (int mt = 0; mt < 2; mt++) {
                const float* xrow0 = xr + (px0 + mt * 16 + r) * XSTRIDE + k8 * 8 + q;
                const float* xrow1 = xrow0 + 8 * XSTRIDE;
                a[mt][0] = __float_as_uint(xrow0[0]);
                a[mt][1] = __float_as_uint(xrow1[0]);
                a[mt][2] = __float_as_uint(xrow0[4]);
                a[mt][3] = __float_as_uint(xrow1[4]);
            }
            uint32_t bf[4][2][4];
            #pragma unroll
            for (int g4 = 0; g4 < 4; g4++) {
                #pragma unroll
                for (int koff = 0; koff < 2; koff++) {
                    int blk = (k8 * 2 + koff) * 8 + nh * 4 + g4;
                    float4 v = *(const float4*)(sB + (blk * 32 + q * 8 + r) * 4);
                    bf[g4][koff][0] = __float_as_uint(v.x);
                    bf[g4][koff][1] = __float_as_uint(v.y);
                    bf[g4][koff][2] = __float_as_uint(v.z);
                    bf[g4][koff][3] = __float_as_uint(v.w);
                }
            }
            #pragma unroll
            for (int mt = 0; mt < 2; mt++)
                #pragma unroll
                for (int nt = 0; nt < 16; nt++)
                    mma8(acc[mt][nt], a[mt], bf[nt >> 2][0][nt & 3], bf[nt >> 2][1][nt & 3]);
        }

        // relu * w3 partial sums: s[mt][rowhalf]
        float s[2][2] = {{0.f, 0.f}, {0.f, 0.f}};
        #pragma unroll
        for (int nt = 0; nt < 16; nt++) {
            int n0 = nh * 128 + nt * 8 + q * 2;
            float w3a = w3s[n0], w3b = w3s[n0 + 1];
            #pragma unroll
            for (int mt = 0; mt < 2; mt++) {
                s[mt][0] = fmaf(fmaxf(acc[mt][nt][0], 0.f), w3a, s[mt][0]);
                s[mt][0] = fmaf(fmaxf(acc[mt][nt][1], 0.f), w3b, s[mt][0]);
                s[mt][1] = fmaf(fmaxf(acc[mt][nt][2], 0.f), w3a, s[mt][1]);
                s[mt][1] = fmaf(fmaxf(acc[mt][nt][3], 0.f), w3b, s[mt][1]);
            }
        }
        #pragma unroll
        for (int mt = 0; mt < 2; mt++)
            #pragma unroll
            for (int h = 0; h < 2; h++) {
                s[mt][h] += __shfl_xor_sync(0xffffffffu, s[mt][h], 1);
                s[mt][h] += __shfl_xor_sync(0xffffffffu, s[mt][h], 2);
            }
        if (q == 0) {
            #pragma unroll
            for (int mt = 0; mt < 2; mt++)
                #pragma unroll
                for (int h = 0; h < 2; h++)
                    sred[(n * 2 + nh) * 128 + px0 + mt * 16 + h * 8 + r] = s[mt][h];
        }
    }
    __syncthreads();

    // ---- sigmoid + normalize + write w ----
    if (tid < 128) {
        int px = tid;
        float g0 = 1.f / (1.f + __expf(-(sred[0 * 128 + px] + sred[1 * 128 + px] + bias3)));
        float g1 = 1.f / (1.f + __expf(-(sred[2 * 128 + px] + sred[3 * 128 + px] + bias3)));
        float g2 = 1.f / (1.f + __expf(-(sred[4 * 128 + px] + sred[5 * 128 + px] + bias3)));
        float inv = 1.f / (g0 + g1 + g2);
        float w0 = g0 * inv, w1 = g1 * inv, w2 = g2 * inv;
        wnm[px] = w0; wnm[128 + px] = w1; wnm[256 + px] = w2;
        float* out_w = out + (size_t)BS * CD * HW;
        out_w[((size_t)b * NR + 0) * HW + p0 + px] = w0;
        out_w[((size_t)b * NR + 1) * HW + p0 + px] = w1;
        out_w[((size_t)b * NR + 2) * HW + p0 + px] = w2;
    }
    __syncthreads();

    // ---- z epilogue: exact fp32 data from gmem (L2-hot) ----
    {
        int px = tid & 127, hf = tid >> 7;
        float w0 = wnm[px], w1 = wnm[128 + px], w2 = wnm[256 + px];
        const float* dbase = data + (size_t)b * NR * CD * HW + p0 + px;
        float* obase = out + (size_t)b * CD * HW + p0 + px;
        #pragma unroll 4
        for (int cc = 0; cc < 32; cc++) {
            int c = hf * 32 + cc;
            float z =       dbase[(size_t)(0 * CD + c) * HW] * w0;
            z = fmaf(dbase[(size_t)(1 * CD + c) * HW], w1, z);
            z = fmaf(dbase[(size_t)(2 * CD + c) * HW], w2, z);
            obase[(size_t)c * HW] = z;
        }
    }
}

extern "C" void kernel_launch(void* const* d_in, const int* in_sizes, int n_in,
                              void* d_out, int out_size) {
    const float* data = (const float*)d_in[0];
    const float* gt   = (const float*)d_in[1];
    const float* W1   = (const float*)d_in[2];
    const float* b1   = (const float*)d_in[3];
    const float* W3   = (const float*)d_in[4];
    const float* b3   = (const float*)d_in[5];
    float* out = (float*)d_out;

    cudaFuncSetAttribute(qnn_kernel, cudaFuncAttributeMaxDynamicSharedMemorySize,
                         SMEM_BYTES);
    qnn_kernel<<<NBLK, THREADS, SMEM_BYTES>>>(data, gt, W1, b1, W3, b3, out);
}

// round 8
// speedup vs baseline: 1.6037x; 1.6037x over previous
#include <cuda_runtime.h>
#include <cstdint>

#define BS 128
#define NR 3
#define CD 64
#define CG 3
#define CH 256
#define KIN 67
#define KTOT 72
#define HW 1024
#define PXT 128
#define THREADS 512
#define NBLK (BS * HW / PXT)   // 1024

// smem layout (floats)
#define SB_OFF   0          // permuted W1^T tf32: 18432
#define XS_OFF   18432      // X tf32 [3][128 px][76] = 29184 (raw W bounce overlays)
#define W3_OFF   47616      // 256
#define SRED_OFF 47872      // [3][4][128] = 1536
#define WNM_OFF  49408      // [3][128] = 384
#define SMEM_FLOATS 49792
#define SMEM_BYTES (SMEM_FLOATS * 4)   // 199168

#define XSTRIDE 76
#define XREF (PXT * XSTRIDE)   // 9728

__device__ __forceinline__ float tf32f(float f) {
    uint32_t r; asm("cvt.rna.tf32.f32 %0, %1;" : "=r"(r) : "f"(f));
    return __uint_as_float(r);
}

__device__ __forceinline__ void mma8(float* d, const uint32_t* a, uint32_t b0, uint32_t b1) {
    asm volatile(
        "mma.sync.aligned.m16n8k8.row.col.f32.tf32.tf32.f32 "
        "{%0,%1,%2,%3}, {%4,%5,%6,%7}, {%8,%9}, {%0,%1,%2,%3};"
        : "+f"(d[0]), "+f"(d[1]), "+f"(d[2]), "+f"(d[3])
        : "r"(a[0]), "r"(a[1]), "r"(a[2]), "r"(a[3]), "r"(b0), "r"(b1));
}

extern __shared__ float sm[];

__global__ __launch_bounds__(THREADS, 1)
void qnn_kernel(const float* __restrict__ data, const float* __restrict__ gt,
                const float* __restrict__ W1, const float* __restrict__ b1,
                const float* __restrict__ W3, const float* __restrict__ b3,
                float* __restrict__ out)
{
    float* sB   = sm + SB_OFF;
    float* xs   = sm + XS_OFF;
    float* raw  = sm + XS_OFF;      // W bounce, stride 69, overlays xs
    float* w3s  = sm + W3_OFF;
    float* sred = sm + SRED_OFF;
    float* wnm  = sm + WNM_OFF;

    const int tid  = threadIdx.x;
    const int lane = tid & 31;
    const int warp = tid >> 5;       // 0..15
    const int mw = warp & 3;         // px block of 32
    const int nq = warp >> 2;        // output quarter of 64
    const int px0 = mw * 32;
    const int r = lane >> 2;         // 0..7
    const int q = lane & 3;          // 0..3
    const int b  = blockIdx.x >> 3;
    const int p0 = (blockIdx.x & 7) * PXT;

    // ---- phase 1: coalesced W1/b1 -> raw[n*69+kk] (conflict-free) ----
    #pragma unroll 1
    for (int it = 0; it < 34; it++) {
        int i = it * THREADS + tid;          // < 256*68 = 17408
        int n = i / 68, kk = i - n * 68;
        float v = (kk < KIN) ? W1[n * KIN + kk] : b1[n];
        raw[n * 69 + kk] = tf32f(v);
    }
    if (tid < CH) w3s[tid] = W3[tid];
    __syncthreads();

    // ---- phase 2: n-fastest scatter to permuted sB (conflict-free both sides) ----
    #pragma unroll 1
    for (int it = 0; it < 36; it++) {
        int i = it * THREADS + tid;          // < 256*72 = 18432
        int n = i & 255, kk = i >> 8;
        float v = (kk < 68) ? raw[n * 69 + kk] : 0.f;
        int k8 = kk >> 3, koff = (kk >> 2) & 1, k2 = kk & 3;
        int g = n >> 5, j = (n >> 3) & 3, c = n & 7;
        int blk = (k8 * 2 + koff) * 8 + g;
        sB[(blk * 32 + k2 * 8 + c) * 4 + j] = v;
    }
    const float bias3 = b3[0];
    __syncthreads();    // raw reads done before xs overwrite

    // ---- stage X (3 refs, tf32), bias col 67, zero 68..71 ----
    #pragma unroll 1
    for (int it = 0; it < 54; it++) {
        int i = it * THREADS + tid;          // < 27648
        int n = i / 9216;
        int rem = i - n * 9216;
        int px = rem & 127, k = rem >> 7;    // k 0..71
        float v;
        if (k < CD)       v = data[((size_t)(b * NR + n) * CD + k) * HW + p0 + px];
        else if (k < KIN) v = gt[((size_t)b * CG + (k - CD)) * HW + p0 + px];
        else              v = (k == KIN) ? 1.f : 0.f;
        xs[n * XREF + px * XSTRIDE + k] = tf32f(v);
    }
    __syncthreads();

    // ---- 3 refs: MMA + per-ref epilogue ----
    #pragma unroll 1
    for (int n = 0; n < NR; n++) {
        float acc[2][8][4];
        #pragma unroll
        for (int mt = 0; mt < 2; mt++)
            #pragma unroll
            for (int nt = 0; nt < 8; nt++)
                #pragma unroll
                for (int e = 0; e < 4; e++) acc[mt][nt][e] = 0.f;

        const float* xr = xs + n * XREF;

        #pragma unroll
        for (int k8 = 0; k8 < 9; k8++) {
            uint32_t a[2][4];
            #pragma unroll
            for (int mt = 0; mt < 2; mt++) {
                const float* xrow0 = xr + (px0 + mt * 16 + r) * XSTRIDE + k8 * 8 + q;
                const float* xrow1 = xrow0 + 8 * XSTRIDE;
                a[mt][0] = __float_as_uint(xrow0[0]);
                a[mt][1] = __float_as_uint(xrow1[0]);
                a[mt][2] = __float_as_uint(xrow0[4]);
                a[mt][3] = __float_as_uint(xrow1[4]);
            }
            uint32_t bf[2][2][4];
            #pragma unroll
            for (int g4 = 0; g4 < 2; g4++) {
                #pragma unroll
                for (int koff = 0; koff < 2; koff++) {
                    int blk = (k8 * 2 + koff) * 8 + nq * 2 + g4;
                    float4 v = *(const float4*)(sB + (blk * 32 + q * 8 + r) * 4);
                    bf[g4][koff][0] = __float_as_uint(v.x);
                    bf[g4][koff][1] = __float_as_uint(v.y);
                    bf[g4][koff][2] = __float_as_uint(v.z);
                    bf[g4][koff][3] = __float_as_uint(v.w);
                }
            }
            #pragma unroll
            for (int mt = 0; mt < 2; mt++)
                #pragma unroll
                for (int nt = 0; nt < 8; nt++)
                    mma8(acc[mt][nt], a[mt], bf[nt >> 2][0][nt & 3], bf[nt >> 2][1][nt & 3]);
        }

        // relu * w3 partial sums
        float s[2][2] = {{0.f, 0.f}, {0.f, 0.f}};
        #pragma unroll
        for (int nt = 0; nt < 8; nt++) {
            int n0 = nq * 64 + nt * 8 + q * 2;
            float w3a = w3s[n0], w3b = w3s[n0 + 1];
            #pragma unroll
            for (int mt = 0; mt < 2; mt++) {
                s[mt][0] = fmaf(fmaxf(acc[mt][nt][0], 0.f), w3a, s[mt][0]);
                s[mt][0] = fmaf(fmaxf(acc[mt][nt][1], 0.f), w3b, s[mt][0]);
                s[mt][1] = fmaf(fmaxf(acc[mt][nt][2], 0.f), w3a, s[mt][1]);
                s[mt][1] = fmaf(fmaxf(acc[mt][nt][3], 0.f), w3b, s[mt][1]);
            }
        }
        #pragma unroll
        for (int mt = 0; mt < 2; mt++)
            #pragma unroll
            for (int h = 0; h < 2; h++) {
                s[mt][h] += __shfl_xor_sync(0xffffffffu, s[mt][h], 1);
                s[mt][h] += __shfl_xor_sync(0xffffffffu, s[mt][h], 2);
            }
        if (q == 0) {
            #pragma unroll
            for (int mt = 0; mt < 2; mt++)
                #pragma unroll
                for (int h = 0; h < 2; h++)
                    sred[(n * 4 + nq) * 128 + px0 + mt * 16 + h * 8 + r] = s[mt][h];
        }
    }
    __syncthreads();

    // ---- sigmoid + normalize + write w ----
    if (tid < 128) {
        int px = tid;
        float t0 = 0.f, t1 = 0.f, t2 = 0.f;
        #pragma unroll
        for (int nq2 = 0; nq2 < 4; nq2++) {
            t0 += sred[(0 * 4 + nq2) * 128 + px];
            t1 += sred[(1 * 4 + nq2) * 128 + px];
            t2 += sred[(2 * 4 + nq2) * 128 + px];
        }
        float g0 = 1.f / (1.f + __expf(-(t0 + bias3)));
        float g1 = 1.f / (1.f + __expf(-(t1 + bias3)));
        float g2 = 1.f / (1.f + __expf(-(t2 + bias3)));
        float inv = 1.f / (g0 + g1 + g2);
        float w0 = g0 * inv, w1 = g1 * inv, w2 = g2 * inv;
        wnm[px] = w0; wnm[128 + px] = w1; wnm[256 + px] = w2;
        float* out_w = out + (size_t)BS * CD * HW;
        out_w[((size_t)b * NR + 0) * HW + p0 + px] = w0;
        out_w[((size_t)b * NR + 1) * HW + p0 + px] = w1;
        out_w[((size_t)b * NR + 2) * HW + p0 + px] = w2;
    }
    __syncthreads();

    // ---- z epilogue: exact fp32 data from gmem (L2-hot), 512 threads ----
    {
        int px = tid & 127, qtr = tid >> 7;
        float w0 = wnm[px], w1 = wnm[128 + px], w2 = wnm[256 + px];
        const float* dbase = data + (size_t)b * NR * CD * HW + p0 + px;
        float* obase = out + (size_t)b * CD * HW + p0 + px;
        #pragma unroll 4
        for (int cc = 0; cc < 16; cc++) {
            int c = qtr * 16 + cc;
            float z =       dbase[(size_t)(0 * CD + c) * HW] * w0;
            z = fmaf(dbase[(size_t)(1 * CD + c) * HW], w1, z);
            z = fmaf(dbase[(size_t)(2 * CD + c) * HW], w2, z);
            obase[(size_t)c * HW] = z;
        }
    }
}

extern "C" void kernel_launch(void* const* d_in, const int* in_sizes, int n_in,
                              void* d_out, int out_size) {
    const float* data = (const float*)d_in[0];
    const float* gt   = (const float*)d_in[1];
    const float* W1   = (const float*)d_in[2];
    const float* b1   = (const float*)d_in[3];
    const float* W3   = (const float*)d_in[4];
    const float* b3   = (const float*)d_in[5];
    float* out = (float*)d_out;

    cudaFuncSetAttribute(qnn_kernel, cudaFuncAttributeMaxDynamicSharedMemorySize,
                         SMEM_BYTES);
    qnn_kernel<<<NBLK, THREADS, SMEM_BYTES>>>(data, gt, W1, b1, W3, b3, out);
}